// round 10
// baseline (speedup 1.0000x reference)
#include <cuda_runtime.h>

// LightGCN 3-layer propagation on GB300 (sm_103a) — CSR gather, deferred output,
// degree-sorted row permutation (Round 7).
//   Build: degree count -> offs scan -> CSR fill; counting-sort rows by degree
//   so the two rows sharing a warp have (almost always) equal degree — removes
//   the ~25% E[max(d1,d2)]/E[d] wasted gather iterations.
//   layer1: hA[r] = sum norm*x[col]          (x = concat(ue,ie))
//   layer2: hB[r] = sum norm*hA[col]
//   layer3: out[r] = 0.25*(x + hA + hB + sum norm*hB[col])

#define NU 200000
#define NI 100000
#define NN 300000
#define DIM 64
#define NE 1200000
#define NBLK ((NN + 1023) / 1024)   // 293 scan blocks
#define NBINS 256

struct Edge { int c; float nm; };

__device__ int   g_cnt[NN];
__device__ int   g_offs[NN];
__device__ int   g_cur[NN];
__device__ int   g_bsum[NBLK];
__device__ float g_dinv[NN];
__device__ Edge  g_edge[NE];
__device__ int   g_hist[NBINS];
__device__ int   g_hcur[NBINS];
__device__ int   g_perm[NN];
__device__ float g_hA[(size_t)NN * DIM];
__device__ float g_hB[(size_t)NN * DIM];

__global__ void k_zero() {
    int i = blockIdx.x * blockDim.x + threadIdx.x;
    if (i < NN) g_cnt[i] = 0;
    if (i < NBINS) g_hist[i] = 0;
}

__global__ void k_count(const int* __restrict__ row) {
    int e = blockIdx.x * blockDim.x + threadIdx.x;
    if (e < NE) atomicAdd(&g_cnt[row[e]], 1);
}

// Block-level exclusive scan of g_cnt; also computes dinv and degree histogram.
__global__ void k_scan1() {
    __shared__ int sh[1024];
    int i = blockIdx.x * 1024 + threadIdx.x;
    int v = (i < NN) ? g_cnt[i] : 0;
    if (i < NN) {
        g_dinv[i] = (v > 0) ? rsqrtf((float)v) : 0.0f;
        atomicAdd(&g_hist[v < NBINS ? v : NBINS - 1], 1);
    }
    sh[threadIdx.x] = v;
    __syncthreads();
    for (int off = 1; off < 1024; off <<= 1) {
        int t = (threadIdx.x >= off) ? sh[threadIdx.x - off] : 0;
        __syncthreads();
        sh[threadIdx.x] += t;
        __syncthreads();
    }
    if (i < NN) g_offs[i] = sh[threadIdx.x] - v;
    if (threadIdx.x == 1023) g_bsum[blockIdx.x] = sh[1023];
}

// Each block sums partials below it for its base; finalize offs + cursors.
__global__ void k_scan2() {
    __shared__ int base_sh;
    int b = blockIdx.x;
    if (threadIdx.x < 32) {
        int s = 0;
        for (int j = threadIdx.x; j < b; j += 32) s += g_bsum[j];
        #pragma unroll
        for (int o = 16; o; o >>= 1) s += __shfl_down_sync(0xffffffffu, s, o);
        if (threadIdx.x == 0) base_sh = s;
    }
    __syncthreads();
    int i = b * 1024 + threadIdx.x;
    if (i < NN) {
        int o = g_offs[i] + base_sh;
        g_offs[i] = o;
        g_cur[i]  = o;
    }
}

// Exclusive scan of the 256-bin degree histogram (1 block).
__global__ void k_hscan() {
    __shared__ int sh[NBINS];
    int i = threadIdx.x;
    int v = g_hist[i];
    sh[i] = v;
    __syncthreads();
    for (int off = 1; off < NBINS; off <<= 1) {
        int t = (i >= off) ? sh[i - off] : 0;
        __syncthreads();
        sh[i] += t;
        __syncthreads();
    }
    g_hcur[i] = sh[i] - v;
}

// Counting-sort scatter: rows grouped by degree.
__global__ void k_perm() {
    int i = blockIdx.x * blockDim.x + threadIdx.x;
    if (i < NN) {
        int d = g_cnt[i];
        int key = d < NBINS ? d : NBINS - 1;
        int pos = atomicAdd(&g_hcur[key], 1);
        g_perm[pos] = i;
    }
}

__global__ void k_fill(const int* __restrict__ row, const int* __restrict__ col) {
    int e = blockIdx.x * blockDim.x + threadIdx.x;
    if (e < NE) {
        int r = row[e], c = col[e];
        int pos = atomicAdd(&g_cur[r], 1);
        Edge ed;
        ed.c  = c;
        ed.nm = __ldg(&g_dinv[r]) * __ldg(&g_dinv[c]);
        g_edge[pos] = ed;
    }
}

// --- Gather core: 16 lanes per row, one float4 (LDG.128) slice per lane. ---

__device__ __forceinline__ float4 fetch_f4(
    int c, int li, const float4* __restrict__ ue, const float4* __restrict__ ie,
    const float4* __restrict__ src, int fromEmb)
{
    if (fromEmb)
        return (c < NU) ? __ldg(&ue[(size_t)c * 16 + li])
                        : __ldg(&ie[(size_t)(c - NU) * 16 + li]);
    return __ldg(&src[(size_t)c * 16 + li]);
}

__device__ __forceinline__ float4 row_gather(
    int r, int li, const float4* __restrict__ ue, const float4* __restrict__ ie,
    const float4* __restrict__ src, int fromEmb)
{
    int start = g_offs[r];
    int cnt   = g_cnt[r];
    const int2* __restrict__ ep = reinterpret_cast<const int2*>(g_edge) + start;

    float4 acc = make_float4(0.f, 0.f, 0.f, 0.f);
    int j = 0;
    // 4-wide: batch the edge loads, then the v gathers (MLP~4), then FMAs.
    for (; j + 3 < cnt; j += 4) {
        int2 e0 = __ldg(&ep[j + 0]);
        int2 e1 = __ldg(&ep[j + 1]);
        int2 e2 = __ldg(&ep[j + 2]);
        int2 e3 = __ldg(&ep[j + 3]);
        float4 v0 = fetch_f4(e0.x, li, ue, ie, src, fromEmb);
        float4 v1 = fetch_f4(e1.x, li, ue, ie, src, fromEmb);
        float4 v2 = fetch_f4(e2.x, li, ue, ie, src, fromEmb);
        float4 v3 = fetch_f4(e3.x, li, ue, ie, src, fromEmb);
        float n0 = __int_as_float(e0.y), n1 = __int_as_float(e1.y);
        float n2 = __int_as_float(e2.y), n3 = __int_as_float(e3.y);
        acc.x += n0 * v0.x; acc.y += n0 * v0.y; acc.z += n0 * v0.z; acc.w += n0 * v0.w;
        acc.x += n1 * v1.x; acc.y += n1 * v1.y; acc.z += n1 * v1.z; acc.w += n1 * v1.w;
        acc.x += n2 * v2.x; acc.y += n2 * v2.y; acc.z += n2 * v2.z; acc.w += n2 * v2.w;
        acc.x += n3 * v3.x; acc.y += n3 * v3.y; acc.z += n3 * v3.z; acc.w += n3 * v3.w;
    }
    if (j + 1 < cnt) {   // 2-wide step
        int2 e0 = __ldg(&ep[j + 0]);
        int2 e1 = __ldg(&ep[j + 1]);
        float4 v0 = fetch_f4(e0.x, li, ue, ie, src, fromEmb);
        float4 v1 = fetch_f4(e1.x, li, ue, ie, src, fromEmb);
        float n0 = __int_as_float(e0.y), n1 = __int_as_float(e1.y);
        acc.x += n0 * v0.x; acc.y += n0 * v0.y; acc.z += n0 * v0.z; acc.w += n0 * v0.w;
        acc.x += n1 * v1.x; acc.y += n1 * v1.y; acc.z += n1 * v1.z; acc.w += n1 * v1.w;
        j += 2;
    }
    if (j < cnt) {       // final single
        int2 e0 = __ldg(&ep[j]);
        float4 v0 = fetch_f4(e0.x, li, ue, ie, src, fromEmb);
        float n0 = __int_as_float(e0.y);
        acc.x += n0 * v0.x; acc.y += n0 * v0.y; acc.z += n0 * v0.z; acc.w += n0 * v0.w;
    }
    return acc;
}

// Layer 1: hA = A_norm @ x   (rows processed in degree-sorted order)
__global__ void __launch_bounds__(256) k_layer1(
    const float4* __restrict__ ue, const float4* __restrict__ ie)
{
    int t = blockIdx.x * blockDim.x + threadIdx.x;
    int p = t >> 4;
    if (p >= NN) return;
    int r  = __ldg(&g_perm[p]);
    int li = t & 15;
    float4 acc = row_gather(r, li, ue, ie, nullptr, 1);
    reinterpret_cast<float4*>(g_hA)[(size_t)r * 16 + li] = acc;
}

// Layer 2: hB = A_norm @ hA
__global__ void __launch_bounds__(256) k_layer2() {
    int t = blockIdx.x * blockDim.x + threadIdx.x;
    int p = t >> 4;
    if (p >= NN) return;
    int r  = __ldg(&g_perm[p]);
    int li = t & 15;
    float4 acc = row_gather(r, li, nullptr, nullptr, (const float4*)g_hA, 0);
    reinterpret_cast<float4*>(g_hB)[(size_t)r * 16 + li] = acc;
}

// Layer 3: out = 0.25 * (x + hA + hB + A_norm @ hB)
__global__ void __launch_bounds__(256) k_layer3(
    const float4* __restrict__ ue, const float4* __restrict__ ie,
    float4* __restrict__ out)
{
    int t = blockIdx.x * blockDim.x + threadIdx.x;
    int p = t >> 4;
    if (p >= NN) return;
    int r  = __ldg(&g_perm[p]);
    int li = t & 15;

    float4 h3 = row_gather(r, li, nullptr, nullptr, (const float4*)g_hB, 0);

    size_t oi = (size_t)r * 16 + li;
    float4 x  = (r < NU) ? __ldg(&ue[oi]) : __ldg(&ie[(size_t)(r - NU) * 16 + li]);
    float4 h1 = reinterpret_cast<const float4*>(g_hA)[oi];
    float4 h2 = reinterpret_cast<const float4*>(g_hB)[oi];

    float4 o;
    o.x = 0.25f * (x.x + h1.x + h2.x + h3.x);
    o.y = 0.25f * (x.y + h1.y + h2.y + h3.y);
    o.z = 0.25f * (x.z + h1.z + h2.z + h3.z);
    o.w = 0.25f * (x.w + h1.w + h2.w + h3.w);
    out[oi] = o;
}

extern "C" void kernel_launch(void* const* d_in, const int* in_sizes, int n_in,
                              void* d_out, int out_size) {
    const float* ue = (const float*)d_in[0];
    const float* ie = (const float*)d_in[1];
    const int*   ei = (const int*)d_in[2];
    const int* row = ei;
    const int* col = ei + NE;
    float4* out = (float4*)d_out;

    const int B = 256;
    const int gN = (NN + B - 1) / B;
    const int gE = (NE + B - 1) / B;
    const int gL = ((NN * 16) + B - 1) / B;   // 16 lanes per row

    // CSR build + degree counting sort
    k_zero<<<gN, B>>>();
    k_count<<<gE, B>>>(row);
    k_scan1<<<NBLK, 1024>>>();
    k_scan2<<<NBLK, 1024>>>();
    k_hscan<<<1, NBINS>>>();
    k_perm<<<gN, B>>>();
    k_fill<<<gE, B>>>(row, col);

    // Layers
    k_layer1<<<gL, B>>>((const float4*)ue, (const float4*)ie);
    k_layer2<<<gL, B>>>();
    k_layer3<<<gL, B>>>((const float4*)ue, (const float4*)ie, out);
}

// round 11
// speedup vs baseline: 1.2365x; 1.2365x over previous
#include <cuda_runtime.h>

// LightGCN 3-layer propagation on GB300 (sm_103a) — CSR gather, deferred output.
// Round 10: revert degree-sort (regression); Round-7 structure + paired int4
// edge loads (2 edges per LDG.128, 25% fewer LDG issues in the hot loop).
//   layer1: hA[r] = sum norm*x[col]          (x = concat(ue,ie))
//   layer2: hB[r] = sum norm*hA[col]
//   layer3: out[r] = 0.25*(x + hA + hB + sum norm*hB[col])

#define NU 200000
#define NI 100000
#define NN 300000
#define DIM 64
#define NE 1200000
#define NBLK ((NN + 1023) / 1024)   // 293 scan blocks

struct Edge { int c; float nm; };

__device__ int   g_cnt[NN];
__device__ int   g_offs[NN];
__device__ int   g_cur[NN];
__device__ int   g_bsum[NBLK];
__device__ float g_dinv[NN];
__device__ __align__(16) Edge g_edge[NE];
__device__ float g_hA[(size_t)NN * DIM];
__device__ float g_hB[(size_t)NN * DIM];

__global__ void k_zero_cnt() {
    int i = blockIdx.x * blockDim.x + threadIdx.x;
    if (i < NN) g_cnt[i] = 0;
}

__global__ void k_count(const int* __restrict__ row) {
    int e = blockIdx.x * blockDim.x + threadIdx.x;
    if (e < NE) atomicAdd(&g_cnt[row[e]], 1);
}

// Block-level exclusive scan of g_cnt; also computes dinv.
__global__ void k_scan1() {
    __shared__ int sh[1024];
    int i = blockIdx.x * 1024 + threadIdx.x;
    int v = (i < NN) ? g_cnt[i] : 0;
    if (i < NN) g_dinv[i] = (v > 0) ? rsqrtf((float)v) : 0.0f;
    sh[threadIdx.x] = v;
    __syncthreads();
    for (int off = 1; off < 1024; off <<= 1) {
        int t = (threadIdx.x >= off) ? sh[threadIdx.x - off] : 0;
        __syncthreads();
        sh[threadIdx.x] += t;
        __syncthreads();
    }
    if (i < NN) g_offs[i] = sh[threadIdx.x] - v;
    if (threadIdx.x == 1023) g_bsum[blockIdx.x] = sh[1023];
}

// Each block sums the partials below it for its base; finalize offs + cursors.
__global__ void k_scan2() {
    __shared__ int base_sh;
    int b = blockIdx.x;
    if (threadIdx.x < 32) {
        int s = 0;
        for (int j = threadIdx.x; j < b; j += 32) s += g_bsum[j];
        #pragma unroll
        for (int o = 16; o; o >>= 1) s += __shfl_down_sync(0xffffffffu, s, o);
        if (threadIdx.x == 0) base_sh = s;
    }
    __syncthreads();
    int i = b * 1024 + threadIdx.x;
    if (i < NN) {
        int o = g_offs[i] + base_sh;
        g_offs[i] = o;
        g_cur[i]  = o;
    }
}

__global__ void k_fill(const int* __restrict__ row, const int* __restrict__ col) {
    int e = blockIdx.x * blockDim.x + threadIdx.x;
    if (e < NE) {
        int r = row[e], c = col[e];
        int pos = atomicAdd(&g_cur[r], 1);
        Edge ed;
        ed.c  = c;
        ed.nm = __ldg(&g_dinv[r]) * __ldg(&g_dinv[c]);
        g_edge[pos] = ed;
    }
}

// --- Gather core: 16 lanes per row, one float4 (LDG.128) slice per lane. ---

__device__ __forceinline__ float4 fetch_f4(
    int c, int li, const float4* __restrict__ ue, const float4* __restrict__ ie,
    const float4* __restrict__ src, int fromEmb)
{
    if (fromEmb)
        return (c < NU) ? __ldg(&ue[(size_t)c * 16 + li])
                        : __ldg(&ie[(size_t)(c - NU) * 16 + li]);
    return __ldg(&src[(size_t)c * 16 + li]);
}

__device__ __forceinline__ void fma4(float4& acc, float nm, const float4& v) {
    acc.x += nm * v.x; acc.y += nm * v.y; acc.z += nm * v.z; acc.w += nm * v.w;
}

__device__ __forceinline__ float4 row_gather(
    int r, int li, const float4* __restrict__ ue, const float4* __restrict__ ie,
    const float4* __restrict__ src, int fromEmb)
{
    int start = g_offs[r];
    int cnt   = g_cnt[r];
    const Edge* __restrict__ ep = g_edge + start;

    float4 acc = make_float4(0.f, 0.f, 0.f, 0.f);
    int j = 0;

    // Alignment head: make (start + j) even so int4 loads are 16B-aligned.
    if ((start & 1) && cnt > 0) {
        int2 e0 = __ldg(reinterpret_cast<const int2*>(ep));
        float4 v0 = fetch_f4(e0.x, li, ue, ie, src, fromEmb);
        fma4(acc, __int_as_float(e0.y), v0);
        j = 1;
    }

    // 4 edges per iter via 2x int4 (2 edges each); v gathers batched (MLP~4).
    for (; j + 3 < cnt; j += 4) {
        int4 p0 = __ldg(reinterpret_cast<const int4*>(ep + j));       // edges j, j+1
        int4 p1 = __ldg(reinterpret_cast<const int4*>(ep + j + 2));   // edges j+2, j+3
        float4 v0 = fetch_f4(p0.x, li, ue, ie, src, fromEmb);
        float4 v1 = fetch_f4(p0.z, li, ue, ie, src, fromEmb);
        float4 v2 = fetch_f4(p1.x, li, ue, ie, src, fromEmb);
        float4 v3 = fetch_f4(p1.z, li, ue, ie, src, fromEmb);
        fma4(acc, __int_as_float(p0.y), v0);
        fma4(acc, __int_as_float(p0.w), v1);
        fma4(acc, __int_as_float(p1.y), v2);
        fma4(acc, __int_as_float(p1.w), v3);
    }
    if (j + 1 < cnt) {   // one aligned pair
        int4 p0 = __ldg(reinterpret_cast<const int4*>(ep + j));
        float4 v0 = fetch_f4(p0.x, li, ue, ie, src, fromEmb);
        float4 v1 = fetch_f4(p0.z, li, ue, ie, src, fromEmb);
        fma4(acc, __int_as_float(p0.y), v0);
        fma4(acc, __int_as_float(p0.w), v1);
        j += 2;
    }
    if (j < cnt) {       // final single
        int2 e0 = __ldg(reinterpret_cast<const int2*>(ep + j));
        float4 v0 = fetch_f4(e0.x, li, ue, ie, src, fromEmb);
        fma4(acc, __int_as_float(e0.y), v0);
    }
    return acc;
}

// Layer 1: hA = A_norm @ x
__global__ void __launch_bounds__(256) k_layer1(
    const float4* __restrict__ ue, const float4* __restrict__ ie)
{
    int t = blockIdx.x * blockDim.x + threadIdx.x;
    int r = t >> 4;
    if (r >= NN) return;
    int li = t & 15;
    float4 acc = row_gather(r, li, ue, ie, nullptr, 1);
    reinterpret_cast<float4*>(g_hA)[(size_t)r * 16 + li] = acc;
}

// Layer 2: hB = A_norm @ hA
__global__ void __launch_bounds__(256) k_layer2() {
    int t = blockIdx.x * blockDim.x + threadIdx.x;
    int r = t >> 4;
    if (r >= NN) return;
    int li = t & 15;
    float4 acc = row_gather(r, li, nullptr, nullptr, (const float4*)g_hA, 0);
    reinterpret_cast<float4*>(g_hB)[(size_t)r * 16 + li] = acc;
}

// Layer 3: out = 0.25 * (x + hA + hB + A_norm @ hB)
__global__ void __launch_bounds__(256) k_layer3(
    const float4* __restrict__ ue, const float4* __restrict__ ie,
    float4* __restrict__ out)
{
    int t = blockIdx.x * blockDim.x + threadIdx.x;
    int r = t >> 4;
    if (r >= NN) return;
    int li = t & 15;

    float4 h3 = row_gather(r, li, nullptr, nullptr, (const float4*)g_hB, 0);

    size_t oi = (size_t)r * 16 + li;
    float4 x  = (r < NU) ? __ldg(&ue[oi]) : __ldg(&ie[(size_t)(r - NU) * 16 + li]);
    float4 h1 = reinterpret_cast<const float4*>(g_hA)[oi];
    float4 h2 = reinterpret_cast<const float4*>(g_hB)[oi];

    float4 o;
    o.x = 0.25f * (x.x + h1.x + h2.x + h3.x);
    o.y = 0.25f * (x.y + h1.y + h2.y + h3.y);
    o.z = 0.25f * (x.z + h1.z + h2.z + h3.z);
    o.w = 0.25f * (x.w + h1.w + h2.w + h3.w);
    out[oi] = o;
}

extern "C" void kernel_launch(void* const* d_in, const int* in_sizes, int n_in,
                              void* d_out, int out_size) {
    const float* ue = (const float*)d_in[0];
    const float* ie = (const float*)d_in[1];
    const int*   ei = (const int*)d_in[2];
    const int* row = ei;
    const int* col = ei + NE;
    float4* out = (float4*)d_out;

    const int B = 256;
    const int gN = (NN + B - 1) / B;
    const int gE = (NE + B - 1) / B;
    const int gL = ((NN * 16) + B - 1) / B;   // 16 lanes per row

    // CSR build
    k_zero_cnt<<<gN, B>>>();
    k_count<<<gE, B>>>(row);
    k_scan1<<<NBLK, 1024>>>();
    k_scan2<<<NBLK, 1024>>>();
    k_fill<<<gE, B>>>(row, col);

    // Layers
    k_layer1<<<gL, B>>>((const float4*)ue, (const float4*)ie);
    k_layer2<<<gL, B>>>();
    k_layer3<<<gL, B>>>((const float4*)ue, (const float4*)ie, out);
}

// round 12
// speedup vs baseline: 1.6192x; 1.3095x over previous
#include <cuda_runtime.h>
#include <cuda_fp16.h>

// LightGCN 3-layer propagation on GB300 (sm_103a) — CSR gather, deferred output.
// Round 11: Round-7 structure (16 lanes/row, int2 edge loads, 4-wide MLP loop),
// intermediate h-tables stored as fp16 (accumulate fp32). Both ping-pong tables
// (38.4 MB each) + edge stream now fit in L2 -> random gathers become L2 hits.
//   layer1: hA[r] = sum norm*x[col]          (x = concat(ue,ie), fp32 in)
//   layer2: hB[r] = sum norm*hA[col]
//   layer3: out[r] = 0.25*(x + hA + hB + sum norm*hB[col])   (fp32 out)

#define NU 200000
#define NI 100000
#define NN 300000
#define DIM 64
#define NE 1200000
#define NBLK ((NN + 1023) / 1024)   // 293 scan blocks

struct Edge { int c; float nm; };

__device__ int   g_cnt[NN];
__device__ int   g_offs[NN];
__device__ int   g_cur[NN];
__device__ int   g_bsum[NBLK];
__device__ float g_dinv[NN];
__device__ Edge  g_edge[NE];
__device__ __half g_hA[(size_t)NN * DIM];   // 38.4 MB
__device__ __half g_hB[(size_t)NN * DIM];   // 38.4 MB

__global__ void k_zero_cnt() {
    int i = blockIdx.x * blockDim.x + threadIdx.x;
    if (i < NN) g_cnt[i] = 0;
}

__global__ void k_count(const int* __restrict__ row) {
    int e = blockIdx.x * blockDim.x + threadIdx.x;
    if (e < NE) atomicAdd(&g_cnt[row[e]], 1);
}

// Block-level exclusive scan of g_cnt; also computes dinv.
__global__ void k_scan1() {
    __shared__ int sh[1024];
    int i = blockIdx.x * 1024 + threadIdx.x;
    int v = (i < NN) ? g_cnt[i] : 0;
    if (i < NN) g_dinv[i] = (v > 0) ? rsqrtf((float)v) : 0.0f;
    sh[threadIdx.x] = v;
    __syncthreads();
    for (int off = 1; off < 1024; off <<= 1) {
        int t = (threadIdx.x >= off) ? sh[threadIdx.x - off] : 0;
        __syncthreads();
        sh[threadIdx.x] += t;
        __syncthreads();
    }
    if (i < NN) g_offs[i] = sh[threadIdx.x] - v;
    if (threadIdx.x == 1023) g_bsum[blockIdx.x] = sh[1023];
}

// Each block sums the partials below it for its base; finalize offs + cursors.
__global__ void k_scan2() {
    __shared__ int base_sh;
    int b = blockIdx.x;
    if (threadIdx.x < 32) {
        int s = 0;
        for (int j = threadIdx.x; j < b; j += 32) s += g_bsum[j];
        #pragma unroll
        for (int o = 16; o; o >>= 1) s += __shfl_down_sync(0xffffffffu, s, o);
        if (threadIdx.x == 0) base_sh = s;
    }
    __syncthreads();
    int i = b * 1024 + threadIdx.x;
    if (i < NN) {
        int o = g_offs[i] + base_sh;
        g_offs[i] = o;
        g_cur[i]  = o;
    }
}

__global__ void k_fill(const int* __restrict__ row, const int* __restrict__ col) {
    int e = blockIdx.x * blockDim.x + threadIdx.x;
    if (e < NE) {
        int r = row[e], c = col[e];
        int pos = atomicAdd(&g_cur[r], 1);
        Edge ed;
        ed.c  = c;
        ed.nm = __ldg(&g_dinv[r]) * __ldg(&g_dinv[c]);
        g_edge[pos] = ed;
    }
}

// ---------- helpers: 16 lanes per row, lane li owns cols [li*4, li*4+4) ----------

// fp32 source (embeddings): one float4 per lane.
__device__ __forceinline__ float4 fetch_emb(
    int c, int li, const float4* __restrict__ ue, const float4* __restrict__ ie)
{
    return (c < NU) ? __ldg(&ue[(size_t)c * 16 + li])
                    : __ldg(&ie[(size_t)(c - NU) * 16 + li]);
}

// fp16 source (h tables): one uint2 (4 halves) per lane, expanded to float4.
__device__ __forceinline__ float4 fetch_h16(const uint2* __restrict__ src,
                                            int c, int li)
{
    uint2 u = __ldg(&src[(size_t)c * 16 + li]);
    half2 lo = *reinterpret_cast<half2*>(&u.x);
    half2 hi = *reinterpret_cast<half2*>(&u.y);
    float2 a = __half22float2(lo);
    float2 b = __half22float2(hi);
    return make_float4(a.x, a.y, b.x, b.y);
}

__device__ __forceinline__ void fma4(float4& acc, float nm, const float4& v) {
    acc.x += nm * v.x; acc.y += nm * v.y; acc.z += nm * v.z; acc.w += nm * v.w;
}

__device__ __forceinline__ uint2 pack_h16(const float4& v) {
    half2 lo = __floats2half2_rn(v.x, v.y);
    half2 hi = __floats2half2_rn(v.z, v.w);
    uint2 u;
    u.x = *reinterpret_cast<unsigned int*>(&lo);
    u.y = *reinterpret_cast<unsigned int*>(&hi);
    return u;
}

// Gather over fp32 embeddings (layer 1). 4-wide MLP pipeline.
__device__ __forceinline__ float4 row_gather_emb(
    int r, int li, const float4* __restrict__ ue, const float4* __restrict__ ie)
{
    int start = g_offs[r];
    int cnt   = g_cnt[r];
    const int2* __restrict__ ep = reinterpret_cast<const int2*>(g_edge) + start;

    float4 acc = make_float4(0.f, 0.f, 0.f, 0.f);
    int j = 0;
    for (; j + 3 < cnt; j += 4) {
        int2 e0 = __ldg(&ep[j + 0]);
        int2 e1 = __ldg(&ep[j + 1]);
        int2 e2 = __ldg(&ep[j + 2]);
        int2 e3 = __ldg(&ep[j + 3]);
        float4 v0 = fetch_emb(e0.x, li, ue, ie);
        float4 v1 = fetch_emb(e1.x, li, ue, ie);
        float4 v2 = fetch_emb(e2.x, li, ue, ie);
        float4 v3 = fetch_emb(e3.x, li, ue, ie);
        fma4(acc, __int_as_float(e0.y), v0);
        fma4(acc, __int_as_float(e1.y), v1);
        fma4(acc, __int_as_float(e2.y), v2);
        fma4(acc, __int_as_float(e3.y), v3);
    }
    if (j + 1 < cnt) {
        int2 e0 = __ldg(&ep[j + 0]);
        int2 e1 = __ldg(&ep[j + 1]);
        float4 v0 = fetch_emb(e0.x, li, ue, ie);
        float4 v1 = fetch_emb(e1.x, li, ue, ie);
        fma4(acc, __int_as_float(e0.y), v0);
        fma4(acc, __int_as_float(e1.y), v1);
        j += 2;
    }
    if (j < cnt) {
        int2 e0 = __ldg(&ep[j]);
        float4 v0 = fetch_emb(e0.x, li, ue, ie);
        fma4(acc, __int_as_float(e0.y), v0);
    }
    return acc;
}

// Gather over an fp16 h table (layers 2, 3). 4-wide MLP pipeline.
__device__ __forceinline__ float4 row_gather_h16(
    int r, int li, const uint2* __restrict__ src)
{
    int start = g_offs[r];
    int cnt   = g_cnt[r];
    const int2* __restrict__ ep = reinterpret_cast<const int2*>(g_edge) + start;

    float4 acc = make_float4(0.f, 0.f, 0.f, 0.f);
    int j = 0;
    for (; j + 3 < cnt; j += 4) {
        int2 e0 = __ldg(&ep[j + 0]);
        int2 e1 = __ldg(&ep[j + 1]);
        int2 e2 = __ldg(&ep[j + 2]);
        int2 e3 = __ldg(&ep[j + 3]);
        float4 v0 = fetch_h16(src, e0.x, li);
        float4 v1 = fetch_h16(src, e1.x, li);
        float4 v2 = fetch_h16(src, e2.x, li);
        float4 v3 = fetch_h16(src, e3.x, li);
        fma4(acc, __int_as_float(e0.y), v0);
        fma4(acc, __int_as_float(e1.y), v1);
        fma4(acc, __int_as_float(e2.y), v2);
        fma4(acc, __int_as_float(e3.y), v3);
    }
    if (j + 1 < cnt) {
        int2 e0 = __ldg(&ep[j + 0]);
        int2 e1 = __ldg(&ep[j + 1]);
        float4 v0 = fetch_h16(src, e0.x, li);
        float4 v1 = fetch_h16(src, e1.x, li);
        fma4(acc, __int_as_float(e0.y), v0);
        fma4(acc, __int_as_float(e1.y), v1);
        j += 2;
    }
    if (j < cnt) {
        int2 e0 = __ldg(&ep[j]);
        float4 v0 = fetch_h16(src, e0.x, li);
        fma4(acc, __int_as_float(e0.y), v0);
    }
    return acc;
}

// Layer 1: hA = A_norm @ x   (fp32 embeddings in, fp16 hA out)
__global__ void __launch_bounds__(256) k_layer1(
    const float4* __restrict__ ue, const float4* __restrict__ ie)
{
    int t = blockIdx.x * blockDim.x + threadIdx.x;
    int r = t >> 4;
    if (r >= NN) return;
    int li = t & 15;
    float4 acc = row_gather_emb(r, li, ue, ie);
    reinterpret_cast<uint2*>(g_hA)[(size_t)r * 16 + li] = pack_h16(acc);
}

// Layer 2: hB = A_norm @ hA   (fp16 in/out, fp32 accumulate)
__global__ void __launch_bounds__(256) k_layer2() {
    int t = blockIdx.x * blockDim.x + threadIdx.x;
    int r = t >> 4;
    if (r >= NN) return;
    int li = t & 15;
    float4 acc = row_gather_h16(r, li, reinterpret_cast<const uint2*>(g_hA));
    reinterpret_cast<uint2*>(g_hB)[(size_t)r * 16 + li] = pack_h16(acc);
}

// Layer 3: out = 0.25 * (x + hA + hB + A_norm @ hB)   (fp32 out)
__global__ void __launch_bounds__(256) k_layer3(
    const float4* __restrict__ ue, const float4* __restrict__ ie,
    float4* __restrict__ out)
{
    int t = blockIdx.x * blockDim.x + threadIdx.x;
    int r = t >> 4;
    if (r >= NN) return;
    int li = t & 15;

    float4 h3 = row_gather_h16(r, li, reinterpret_cast<const uint2*>(g_hB));

    size_t oi = (size_t)r * 16 + li;
    float4 x  = (r < NU) ? __ldg(&ue[oi]) : __ldg(&ie[(size_t)(r - NU) * 16 + li]);
    float4 h1 = fetch_h16(reinterpret_cast<const uint2*>(g_hA), r, li);
    float4 h2 = fetch_h16(reinterpret_cast<const uint2*>(g_hB), r, li);

    float4 o;
    o.x = 0.25f * (x.x + h1.x + h2.x + h3.x);
    o.y = 0.25f * (x.y + h1.y + h2.y + h3.y);
    o.z = 0.25f * (x.z + h1.z + h2.z + h3.z);
    o.w = 0.25f * (x.w + h1.w + h2.w + h3.w);
    out[oi] = o;
}

extern "C" void kernel_launch(void* const* d_in, const int* in_sizes, int n_in,
                              void* d_out, int out_size) {
    const float* ue = (const float*)d_in[0];
    const float* ie = (const float*)d_in[1];
    const int*   ei = (const int*)d_in[2];
    const int* row = ei;
    const int* col = ei + NE;
    float4* out = (float4*)d_out;

    const int B = 256;
    const int gN = (NN + B - 1) / B;
    const int gE = (NE + B - 1) / B;
    const int gL = ((NN * 16) + B - 1) / B;   // 16 lanes per row

    // CSR build
    k_zero_cnt<<<gN, B>>>();
    k_count<<<gE, B>>>(row);
    k_scan1<<<NBLK, 1024>>>();
    k_scan2<<<NBLK, 1024>>>();
    k_fill<<<gE, B>>>(row, col);

    // Layers
    k_layer1<<<gL, B>>>((const float4*)ue, (const float4*)ie);
    k_layer2<<<gL, B>>>();
    k_layer3<<<gL, B>>>((const float4*)ue, (const float4*)ie, out);
}

// round 13
// speedup vs baseline: 1.6790x; 1.0369x over previous
#include <cuda_runtime.h>
#include <cuda_fp16.h>

// LightGCN 3-layer propagation on GB300 (sm_103a) — CSR gather, deferred output.
// Round 12: ALL gather sources fp16 + L2-resident. New k_cvt pass converts the
// fp32 embeddings into an fp16 x-table (streaming, ~15us); layer 1 then gathers
// from L2-resident fp16 like layers 2/3 (and loses the concat branch).
//   x16  = fp16(concat(ue, ie))              (streaming convert)
//   layer1: hA[r] = sum norm*x16[col]
//   layer2: hB[r] = sum norm*hA[col]
//   layer3: out[r] = 0.25*(x_fp32 + hA + hB + sum norm*hB[col])

#define NU 200000
#define NI 100000
#define NN 300000
#define DIM 64
#define NE 1200000
#define NBLK ((NN + 1023) / 1024)   // 293 scan blocks

struct Edge { int c; float nm; };

__device__ int   g_cnt[NN];
__device__ int   g_offs[NN];
__device__ int   g_cur[NN];
__device__ int   g_bsum[NBLK];
__device__ float g_dinv[NN];
__device__ Edge  g_edge[NE];
__device__ __half g_x16[(size_t)NN * DIM];  // 38.4 MB fp16 x-table
__device__ __half g_hA[(size_t)NN * DIM];   // 38.4 MB
__device__ __half g_hB[(size_t)NN * DIM];   // 38.4 MB

__global__ void k_zero_cnt() {
    int i = blockIdx.x * blockDim.x + threadIdx.x;
    if (i < NN) g_cnt[i] = 0;
}

__global__ void k_count(const int* __restrict__ row) {
    int e = blockIdx.x * blockDim.x + threadIdx.x;
    if (e < NE) atomicAdd(&g_cnt[row[e]], 1);
}

// Block-level exclusive scan of g_cnt; also computes dinv.
__global__ void k_scan1() {
    __shared__ int sh[1024];
    int i = blockIdx.x * 1024 + threadIdx.x;
    int v = (i < NN) ? g_cnt[i] : 0;
    if (i < NN) g_dinv[i] = (v > 0) ? rsqrtf((float)v) : 0.0f;
    sh[threadIdx.x] = v;
    __syncthreads();
    for (int off = 1; off < 1024; off <<= 1) {
        int t = (threadIdx.x >= off) ? sh[threadIdx.x - off] : 0;
        __syncthreads();
        sh[threadIdx.x] += t;
        __syncthreads();
    }
    if (i < NN) g_offs[i] = sh[threadIdx.x] - v;
    if (threadIdx.x == 1023) g_bsum[blockIdx.x] = sh[1023];
}

// Each block sums the partials below it for its base; finalize offs + cursors.
__global__ void k_scan2() {
    __shared__ int base_sh;
    int b = blockIdx.x;
    if (threadIdx.x < 32) {
        int s = 0;
        for (int j = threadIdx.x; j < b; j += 32) s += g_bsum[j];
        #pragma unroll
        for (int o = 16; o; o >>= 1) s += __shfl_down_sync(0xffffffffu, s, o);
        if (threadIdx.x == 0) base_sh = s;
    }
    __syncthreads();
    int i = b * 1024 + threadIdx.x;
    if (i < NN) {
        int o = g_offs[i] + base_sh;
        g_offs[i] = o;
        g_cur[i]  = o;
    }
}

__global__ void k_fill(const int* __restrict__ row, const int* __restrict__ col) {
    int e = blockIdx.x * blockDim.x + threadIdx.x;
    if (e < NE) {
        int r = row[e], c = col[e];
        int pos = atomicAdd(&g_cur[r], 1);
        Edge ed;
        ed.c  = c;
        ed.nm = __ldg(&g_dinv[r]) * __ldg(&g_dinv[c]);
        g_edge[pos] = ed;
    }
}

// Streaming convert: x16 = fp16(concat(ue, ie)). One float4 -> uint2 per thread.
__global__ void k_cvt(const float4* __restrict__ ue, const float4* __restrict__ ie) {
    int i = blockIdx.x * blockDim.x + threadIdx.x;
    const int NF4 = NN * (DIM / 4);
    if (i >= NF4) return;
    float4 v = (i < NU * (DIM / 4)) ? __ldg(&ue[i]) : __ldg(&ie[i - NU * (DIM / 4)]);
    half2 lo = __floats2half2_rn(v.x, v.y);
    half2 hi = __floats2half2_rn(v.z, v.w);
    uint2 u;
    u.x = *reinterpret_cast<unsigned int*>(&lo);
    u.y = *reinterpret_cast<unsigned int*>(&hi);
    reinterpret_cast<uint2*>(g_x16)[i] = u;
}

// ---------- gather core: 16 lanes per row, lane li owns cols [li*4, li*4+4) ----

__device__ __forceinline__ float4 fetch_h16(const uint2* __restrict__ src,
                                            int c, int li)
{
    uint2 u = __ldg(&src[(size_t)c * 16 + li]);
    half2 lo = *reinterpret_cast<half2*>(&u.x);
    half2 hi = *reinterpret_cast<half2*>(&u.y);
    float2 a = __half22float2(lo);
    float2 b = __half22float2(hi);
    return make_float4(a.x, a.y, b.x, b.y);
}

__device__ __forceinline__ void fma4(float4& acc, float nm, const float4& v) {
    acc.x += nm * v.x; acc.y += nm * v.y; acc.z += nm * v.z; acc.w += nm * v.w;
}

__device__ __forceinline__ uint2 pack_h16(const float4& v) {
    half2 lo = __floats2half2_rn(v.x, v.y);
    half2 hi = __floats2half2_rn(v.z, v.w);
    uint2 u;
    u.x = *reinterpret_cast<unsigned int*>(&lo);
    u.y = *reinterpret_cast<unsigned int*>(&hi);
    return u;
}

// Gather over an fp16 table. 4-wide MLP pipeline (batched edge + v loads).
__device__ __forceinline__ float4 row_gather_h16(
    int r, int li, const uint2* __restrict__ src)
{
    int start = g_offs[r];
    int cnt   = g_cnt[r];
    const int2* __restrict__ ep = reinterpret_cast<const int2*>(g_edge) + start;

    float4 acc = make_float4(0.f, 0.f, 0.f, 0.f);
    int j = 0;
    for (; j + 3 < cnt; j += 4) {
        int2 e0 = __ldg(&ep[j + 0]);
        int2 e1 = __ldg(&ep[j + 1]);
        int2 e2 = __ldg(&ep[j + 2]);
        int2 e3 = __ldg(&ep[j + 3]);
        float4 v0 = fetch_h16(src, e0.x, li);
        float4 v1 = fetch_h16(src, e1.x, li);
        float4 v2 = fetch_h16(src, e2.x, li);
        float4 v3 = fetch_h16(src, e3.x, li);
        fma4(acc, __int_as_float(e0.y), v0);
        fma4(acc, __int_as_float(e1.y), v1);
        fma4(acc, __int_as_float(e2.y), v2);
        fma4(acc, __int_as_float(e3.y), v3);
    }
    if (j + 1 < cnt) {
        int2 e0 = __ldg(&ep[j + 0]);
        int2 e1 = __ldg(&ep[j + 1]);
        float4 v0 = fetch_h16(src, e0.x, li);
        float4 v1 = fetch_h16(src, e1.x, li);
        fma4(acc, __int_as_float(e0.y), v0);
        fma4(acc, __int_as_float(e1.y), v1);
        j += 2;
    }
    if (j < cnt) {
        int2 e0 = __ldg(&ep[j]);
        float4 v0 = fetch_h16(src, e0.x, li);
        fma4(acc, __int_as_float(e0.y), v0);
    }
    return acc;
}

// Layer 1: hA = A_norm @ x16
__global__ void __launch_bounds__(256) k_layer1() {
    int t = blockIdx.x * blockDim.x + threadIdx.x;
    int r = t >> 4;
    if (r >= NN) return;
    int li = t & 15;
    float4 acc = row_gather_h16(r, li, reinterpret_cast<const uint2*>(g_x16));
    reinterpret_cast<uint2*>(g_hA)[(size_t)r * 16 + li] = pack_h16(acc);
}

// Layer 2: hB = A_norm @ hA
__global__ void __launch_bounds__(256) k_layer2() {
    int t = blockIdx.x * blockDim.x + threadIdx.x;
    int r = t >> 4;
    if (r >= NN) return;
    int li = t & 15;
    float4 acc = row_gather_h16(r, li, reinterpret_cast<const uint2*>(g_hA));
    reinterpret_cast<uint2*>(g_hB)[(size_t)r * 16 + li] = pack_h16(acc);
}

// Layer 3: out = 0.25 * (x_fp32 + hA + hB + A_norm @ hB)
__global__ void __launch_bounds__(256) k_layer3(
    const float4* __restrict__ ue, const float4* __restrict__ ie,
    float4* __restrict__ out)
{
    int t = blockIdx.x * blockDim.x + threadIdx.x;
    int r = t >> 4;
    if (r >= NN) return;
    int li = t & 15;

    float4 h3 = row_gather_h16(r, li, reinterpret_cast<const uint2*>(g_hB));

    size_t oi = (size_t)r * 16 + li;
    float4 x  = (r < NU) ? __ldg(&ue[oi]) : __ldg(&ie[(size_t)(r - NU) * 16 + li]);
    float4 h1 = fetch_h16(reinterpret_cast<const uint2*>(g_hA), r, li);
    float4 h2 = fetch_h16(reinterpret_cast<const uint2*>(g_hB), r, li);

    float4 o;
    o.x = 0.25f * (x.x + h1.x + h2.x + h3.x);
    o.y = 0.25f * (x.y + h1.y + h2.y + h3.y);
    o.z = 0.25f * (x.z + h1.z + h2.z + h3.z);
    o.w = 0.25f * (x.w + h1.w + h2.w + h3.w);
    out[oi] = o;
}

extern "C" void kernel_launch(void* const* d_in, const int* in_sizes, int n_in,
                              void* d_out, int out_size) {
    const float* ue = (const float*)d_in[0];
    const float* ie = (const float*)d_in[1];
    const int*   ei = (const int*)d_in[2];
    const int* row = ei;
    const int* col = ei + NE;
    float4* out = (float4*)d_out;

    const int B = 256;
    const int gN  = (NN + B - 1) / B;
    const int gE  = (NE + B - 1) / B;
    const int gF4 = ((NN * (DIM / 4)) + B - 1) / B;
    const int gL  = ((NN * 16) + B - 1) / B;   // 16 lanes per row

    // CSR build + fp16 x-table convert
    k_zero_cnt<<<gN, B>>>();
    k_count<<<gE, B>>>(row);
    k_scan1<<<NBLK, 1024>>>();
    k_scan2<<<NBLK, 1024>>>();
    k_fill<<<gE, B>>>(row, col);
    k_cvt<<<gF4, B>>>((const float4*)ue, (const float4*)ie);

    // Layers
    k_layer1<<<gL, B>>>();
    k_layer2<<<gL, B>>>();
    k_layer3<<<gL, B>>>((const float4*)ue, (const float4*)ie, out);
}

// round 14
// speedup vs baseline: 1.7648x; 1.0511x over previous
#include <cuda_runtime.h>
#include <cuda_fp16.h>

// LightGCN 3-layer propagation on GB300 (sm_103a) — CSR gather, deferred output.
// Round 13: widen per-lane slice to 16B fp16 (8 lanes/row, uint4 gathers).
// Same 128B/line coalescing, half the v-load instructions, 2x in-flight loads
// per warp (4 rows/warp x 4-wide edge batching) -> less L2-latency exposure.
//   x16  = fp16(concat(ue, ie))              (streaming convert)
//   layer1: hA[r] = sum norm*x16[col]
//   layer2: hB[r] = sum norm*hA[col]
//   layer3: out[r] = 0.25*(x_fp32 + hA + hB + sum norm*hB[col])

#define NU 200000
#define NI 100000
#define NN 300000
#define DIM 64
#define NE 1200000
#define NBLK ((NN + 1023) / 1024)   // 293 scan blocks

struct Edge { int c; float nm; };

__device__ int   g_cnt[NN];
__device__ int   g_offs[NN];
__device__ int   g_cur[NN];
__device__ int   g_bsum[NBLK];
__device__ float g_dinv[NN];
__device__ Edge  g_edge[NE];
__device__ __half g_x16[(size_t)NN * DIM];  // 38.4 MB fp16 x-table
__device__ __half g_hA[(size_t)NN * DIM];   // 38.4 MB
__device__ __half g_hB[(size_t)NN * DIM];   // 38.4 MB

__global__ void k_zero_cnt() {
    int i = blockIdx.x * blockDim.x + threadIdx.x;
    if (i < NN) g_cnt[i] = 0;
}

__global__ void k_count(const int* __restrict__ row) {
    int e = blockIdx.x * blockDim.x + threadIdx.x;
    if (e < NE) atomicAdd(&g_cnt[row[e]], 1);
}

// Block-level exclusive scan of g_cnt; also computes dinv.
__global__ void k_scan1() {
    __shared__ int sh[1024];
    int i = blockIdx.x * 1024 + threadIdx.x;
    int v = (i < NN) ? g_cnt[i] : 0;
    if (i < NN) g_dinv[i] = (v > 0) ? rsqrtf((float)v) : 0.0f;
    sh[threadIdx.x] = v;
    __syncthreads();
    for (int off = 1; off < 1024; off <<= 1) {
        int t = (threadIdx.x >= off) ? sh[threadIdx.x - off] : 0;
        __syncthreads();
        sh[threadIdx.x] += t;
        __syncthreads();
    }
    if (i < NN) g_offs[i] = sh[threadIdx.x] - v;
    if (threadIdx.x == 1023) g_bsum[blockIdx.x] = sh[1023];
}

// Each block sums the partials below it for its base; finalize offs + cursors.
__global__ void k_scan2() {
    __shared__ int base_sh;
    int b = blockIdx.x;
    if (threadIdx.x < 32) {
        int s = 0;
        for (int j = threadIdx.x; j < b; j += 32) s += g_bsum[j];
        #pragma unroll
        for (int o = 16; o; o >>= 1) s += __shfl_down_sync(0xffffffffu, s, o);
        if (threadIdx.x == 0) base_sh = s;
    }
    __syncthreads();
    int i = b * 1024 + threadIdx.x;
    if (i < NN) {
        int o = g_offs[i] + base_sh;
        g_offs[i] = o;
        g_cur[i]  = o;
    }
}

__global__ void k_fill(const int* __restrict__ row, const int* __restrict__ col) {
    int e = blockIdx.x * blockDim.x + threadIdx.x;
    if (e < NE) {
        int r = row[e], c = col[e];
        int pos = atomicAdd(&g_cur[r], 1);
        Edge ed;
        ed.c  = c;
        ed.nm = __ldg(&g_dinv[r]) * __ldg(&g_dinv[c]);
        g_edge[pos] = ed;
    }
}

// Streaming convert: x16 = fp16(concat(ue, ie)). One float4 -> uint2 per thread.
__global__ void k_cvt(const float4* __restrict__ ue, const float4* __restrict__ ie) {
    int i = blockIdx.x * blockDim.x + threadIdx.x;
    const int NF4 = NN * (DIM / 4);
    if (i >= NF4) return;
    float4 v = (i < NU * (DIM / 4)) ? __ldg(&ue[i]) : __ldg(&ie[i - NU * (DIM / 4)]);
    half2 lo = __floats2half2_rn(v.x, v.y);
    half2 hi = __floats2half2_rn(v.z, v.w);
    uint2 u;
    u.x = *reinterpret_cast<unsigned int*>(&lo);
    u.y = *reinterpret_cast<unsigned int*>(&hi);
    reinterpret_cast<uint2*>(g_x16)[i] = u;
}

// ---------- gather core: 8 lanes per row, lane li owns cols [li*8, li*8+8) ----
// Each fetch is a uint4 = 8 halves = 16 bytes; 8 lanes cover the 128B row.

struct Acc8 { float4 a, b; };

__device__ __forceinline__ void fetch_u4(const uint4* __restrict__ src,
                                         int c, int li, float4& fa, float4& fb)
{
    uint4 u = __ldg(&src[(size_t)c * 8 + li]);
    half2 h0 = *reinterpret_cast<half2*>(&u.x);
    half2 h1 = *reinterpret_cast<half2*>(&u.y);
    half2 h2 = *reinterpret_cast<half2*>(&u.z);
    half2 h3 = *reinterpret_cast<half2*>(&u.w);
    float2 f0 = __half22float2(h0);
    float2 f1 = __half22float2(h1);
    float2 f2 = __half22float2(h2);
    float2 f3 = __half22float2(h3);
    fa = make_float4(f0.x, f0.y, f1.x, f1.y);
    fb = make_float4(f2.x, f2.y, f3.x, f3.y);
}

__device__ __forceinline__ void fma8(Acc8& acc, float nm,
                                     const float4& va, const float4& vb)
{
    acc.a.x += nm * va.x; acc.a.y += nm * va.y; acc.a.z += nm * va.z; acc.a.w += nm * va.w;
    acc.b.x += nm * vb.x; acc.b.y += nm * vb.y; acc.b.z += nm * vb.z; acc.b.w += nm * vb.w;
}

__device__ __forceinline__ uint4 pack_h8(const Acc8& v) {
    half2 h0 = __floats2half2_rn(v.a.x, v.a.y);
    half2 h1 = __floats2half2_rn(v.a.z, v.a.w);
    half2 h2 = __floats2half2_rn(v.b.x, v.b.y);
    half2 h3 = __floats2half2_rn(v.b.z, v.b.w);
    uint4 u;
    u.x = *reinterpret_cast<unsigned int*>(&h0);
    u.y = *reinterpret_cast<unsigned int*>(&h1);
    u.z = *reinterpret_cast<unsigned int*>(&h2);
    u.w = *reinterpret_cast<unsigned int*>(&h3);
    return u;
}

// Gather over an fp16 table. 4-wide MLP pipeline (batched edge + v loads).
__device__ __forceinline__ Acc8 row_gather_h16(
    int r, int li, const uint4* __restrict__ src)
{
    int start = g_offs[r];
    int cnt   = g_cnt[r];
    const int2* __restrict__ ep = reinterpret_cast<const int2*>(g_edge) + start;

    Acc8 acc;
    acc.a = make_float4(0.f, 0.f, 0.f, 0.f);
    acc.b = make_float4(0.f, 0.f, 0.f, 0.f);
    int j = 0;
    for (; j + 3 < cnt; j += 4) {
        int2 e0 = __ldg(&ep[j + 0]);
        int2 e1 = __ldg(&ep[j + 1]);
        int2 e2 = __ldg(&ep[j + 2]);
        int2 e3 = __ldg(&ep[j + 3]);
        float4 va0, vb0, va1, vb1, va2, vb2, va3, vb3;
        fetch_u4(src, e0.x, li, va0, vb0);
        fetch_u4(src, e1.x, li, va1, vb1);
        fetch_u4(src, e2.x, li, va2, vb2);
        fetch_u4(src, e3.x, li, va3, vb3);
        fma8(acc, __int_as_float(e0.y), va0, vb0);
        fma8(acc, __int_as_float(e1.y), va1, vb1);
        fma8(acc, __int_as_float(e2.y), va2, vb2);
        fma8(acc, __int_as_float(e3.y), va3, vb3);
    }
    if (j + 1 < cnt) {
        int2 e0 = __ldg(&ep[j + 0]);
        int2 e1 = __ldg(&ep[j + 1]);
        float4 va0, vb0, va1, vb1;
        fetch_u4(src, e0.x, li, va0, vb0);
        fetch_u4(src, e1.x, li, va1, vb1);
        fma8(acc, __int_as_float(e0.y), va0, vb0);
        fma8(acc, __int_as_float(e1.y), va1, vb1);
        j += 2;
    }
    if (j < cnt) {
        int2 e0 = __ldg(&ep[j]);
        float4 va0, vb0;
        fetch_u4(src, e0.x, li, va0, vb0);
        fma8(acc, __int_as_float(e0.y), va0, vb0);
    }
    return acc;
}

// Layer 1: hA = A_norm @ x16
__global__ void __launch_bounds__(256) k_layer1() {
    int t = blockIdx.x * blockDim.x + threadIdx.x;
    int r = t >> 3;
    if (r >= NN) return;
    int li = t & 7;
    Acc8 acc = row_gather_h16(r, li, reinterpret_cast<const uint4*>(g_x16));
    reinterpret_cast<uint4*>(g_hA)[(size_t)r * 8 + li] = pack_h8(acc);
}

// Layer 2: hB = A_norm @ hA
__global__ void __launch_bounds__(256) k_layer2() {
    int t = blockIdx.x * blockDim.x + threadIdx.x;
    int r = t >> 3;
    if (r >= NN) return;
    int li = t & 7;
    Acc8 acc = row_gather_h16(r, li, reinterpret_cast<const uint4*>(g_hA));
    reinterpret_cast<uint4*>(g_hB)[(size_t)r * 8 + li] = pack_h8(acc);
}

// Layer 3: out = 0.25 * (x_fp32 + hA + hB + A_norm @ hB)
__global__ void __launch_bounds__(256) k_layer3(
    const float4* __restrict__ ue, const float4* __restrict__ ie,
    float4* __restrict__ out)
{
    int t = blockIdx.x * blockDim.x + threadIdx.x;
    int r = t >> 3;
    if (r >= NN) return;
    int li = t & 7;

    Acc8 h3 = row_gather_h16(r, li, reinterpret_cast<const uint4*>(g_hB));

    // lane owns cols [li*8, li*8+8) = two float4 slots (2*li, 2*li+1)
    size_t oi = (size_t)r * 16 + li * 2;
    float4 xa, xb;
    if (r < NU) {
        xa = __ldg(&ue[oi]); xb = __ldg(&ue[oi + 1]);
    } else {
        size_t ii = (size_t)(r - NU) * 16 + li * 2;
        xa = __ldg(&ie[ii]); xb = __ldg(&ie[ii + 1]);
    }
    float4 h1a, h1b, h2a, h2b;
    fetch_u4(reinterpret_cast<const uint4*>(g_hA), r, li, h1a, h1b);
    fetch_u4(reinterpret_cast<const uint4*>(g_hB), r, li, h2a, h2b);

    float4 oa, ob;
    oa.x = 0.25f * (xa.x + h1a.x + h2a.x + h3.a.x);
    oa.y = 0.25f * (xa.y + h1a.y + h2a.y + h3.a.y);
    oa.z = 0.25f * (xa.z + h1a.z + h2a.z + h3.a.z);
    oa.w = 0.25f * (xa.w + h1a.w + h2a.w + h3.a.w);
    ob.x = 0.25f * (xb.x + h1b.x + h2b.x + h3.b.x);
    ob.y = 0.25f * (xb.y + h1b.y + h2b.y + h3.b.y);
    ob.z = 0.25f * (xb.z + h1b.z + h2b.z + h3.b.z);
    ob.w = 0.25f * (xb.w + h1b.w + h2b.w + h3.b.w);
    out[oi]     = oa;
    out[oi + 1] = ob;
}

extern "C" void kernel_launch(void* const* d_in, const int* in_sizes, int n_in,
                              void* d_out, int out_size) {
    const float* ue = (const float*)d_in[0];
    const float* ie = (const float*)d_in[1];
    const int*   ei = (const int*)d_in[2];
    const int* row = ei;
    const int* col = ei + NE;
    float4* out = (float4*)d_out;

    const int B = 256;
    const int gN  = (NN + B - 1) / B;
    const int gE  = (NE + B - 1) / B;
    const int gF4 = ((NN * (DIM / 4)) + B - 1) / B;
    const int gL  = ((NN * 8) + B - 1) / B;    // 8 lanes per row

    // CSR build + fp16 x-table convert
    k_zero_cnt<<<gN, B>>>();
    k_count<<<gE, B>>>(row);
    k_scan1<<<NBLK, 1024>>>();
    k_scan2<<<NBLK, 1024>>>();
    k_fill<<<gE, B>>>(row, col);
    k_cvt<<<gF4, B>>>((const float4*)ue, (const float4*)ie);

    // Layers
    k_layer1<<<gL, B>>>();
    k_layer2<<<gL, B>>>();
    k_layer3<<<gL, B>>>((const float4*)ue, (const float4*)ie, out);
}